// round 4
// baseline (speedup 1.0000x reference)
#include <cuda_runtime.h>
#include <cuda_fp16.h>

#define EPSV 1e-8f

constexpr int Bb = 64;
constexpr int N0 = 20000, E0 = 200000, M0 = 8000;
constexpr int E1 = 80000,  M1 = 2000;
constexpr int E2 = 20000,  M2 = 500;
constexpr int ETOT = E0 + E1 + E2;
constexpr int MTOT = M0 + M1 + M2;

constexpr int TB = N0 / 32;                    // 625 transpose blocks
constexpr int EB = (ETOT / 4 + 255) / 256;     // edge blocks, 4 edges/thread

// ---- scratch (device globals; zero-initialized at module load) ----
__device__ __half g_xT[N0 * Bb];               // x transposed to (node, batch), fp16
__device__ int    g_cnt[MTOT];                 // degree counters (re-zeroed by k_scan)
__device__ int    g_slot[ETOT];                // per-edge slot within its dst bucket
__device__ int    g_rp0[M0 + 1], g_rp1[M1 + 1], g_rp2[M2 + 1];
__device__ int    g_ce0[E0], g_ce1[E1], g_ce2[E2];
__device__ __half g_d1[M0 * Bb * 8];           // (node, batch, h) fp16
__device__ __half g_d2[M1 * Bb * 8];
__device__ float  g_d3[M2 * Bb * 8];

// ---- K1: transpose x (B,N0) -> (N0,B) fp16  ∥  histogram + slot assignment ----
__global__ void k_pre(const float* __restrict__ x,
                      const int* __restrict__ d0, const int* __restrict__ d1,
                      const int* __restrict__ d2) {
    if (blockIdx.x < TB) {
        __shared__ float tile[64][33];
        int nb = blockIdx.x * 32;
        int tx = threadIdx.x & 31, ty = threadIdx.x >> 5;
#pragma unroll
        for (int i = 0; i < 64; i += 8)
            tile[ty + i][tx] = x[(ty + i) * N0 + nb + tx];
        __syncthreads();
        int r = threadIdx.x >> 3;        // node within tile (0..31)
        int q = threadIdx.x & 7;         // batch octet (0..7)
        __half2 h[4];
#pragma unroll
        for (int k = 0; k < 4; k++)
            h[k] = __floats2half2_rn(tile[q * 8 + 2 * k][r], tile[q * 8 + 2 * k + 1][r]);
        *(uint4*)&g_xT[(nb + r) * Bb + q * 8] = *(uint4*)h;
    } else {
        int i0 = ((blockIdx.x - TB) * 256 + threadIdx.x) * 4;
        if (i0 >= ETOT) return;
        const int* dp; int* cnt; int off;
        if (i0 < E0)            { dp = d0; cnt = g_cnt;            off = 0; }
        else if (i0 < E0 + E1)  { dp = d1; cnt = g_cnt + M0;       off = E0; }
        else                    { dp = d2; cnt = g_cnt + M0 + M1;  off = E0 + E1; }
        int4 dd = *(const int4*)&dp[i0 - off];
        int s0 = atomicAdd(&cnt[dd.x], 1);
        int s1 = atomicAdd(&cnt[dd.y], 1);
        int s2 = atomicAdd(&cnt[dd.z], 1);
        int s3 = atomicAdd(&cnt[dd.w], 1);
        *(int4*)&g_slot[i0] = make_int4(s0, s1, s2, s3);
    }
}

// ---- K2: exclusive scan (warp-shuffle, 8/thread); re-zeroes counters ----
__global__ void k_scan() {
    const int L = blockIdx.x;
    int* cnt    = (L == 0) ? g_cnt  : (L == 1) ? g_cnt + M0 : g_cnt + M0 + M1;
    int* rp     = (L == 0) ? g_rp0  : (L == 1) ? g_rp1      : g_rp2;
    const int m = (L == 0) ? M0     : (L == 1) ? M1         : M2;

    int t = threadIdx.x;
    int base = t * 8;
    int v[8];
    int s = 0;
#pragma unroll
    for (int k = 0; k < 8; k++) {
        int c = (base + k < m) ? cnt[base + k] : 0;
        s += c;
        v[k] = s;
    }
    int lane = t & 31, wid = t >> 5;
    int inc = s;
#pragma unroll
    for (int off = 1; off < 32; off <<= 1) {
        int n = __shfl_up_sync(0xffffffffu, inc, off);
        if (lane >= off) inc += n;
    }
    int wexcl = inc - s;
    __shared__ int wtot[32];
    if (lane == 31) wtot[wid] = inc;
    __syncthreads();
    if (t < 32) {
        int w = wtot[t];
        int wi = w;
#pragma unroll
        for (int off = 1; off < 32; off <<= 1) {
            int n = __shfl_up_sync(0xffffffffu, wi, off);
            if (t >= off) wi += n;
        }
        wtot[t] = wi - w;
    }
    __syncthreads();
    int off0 = wtot[wid] + wexcl;
#pragma unroll
    for (int k = 0; k < 8; k++)
        if (base + k < m) { rp[base + k + 1] = off0 + v[k]; cnt[base + k] = 0; }
    if (t == 0) rp[0] = 0;
}

// ---- K3: fill CSR via precomputed slots (no atomics) ----
__global__ void k_fill(const int* __restrict__ s0, const int* __restrict__ d0,
                       const int* __restrict__ s1, const int* __restrict__ d1,
                       const int* __restrict__ s2, const int* __restrict__ d2) {
    int i0 = (blockIdx.x * 256 + threadIdx.x) * 4;
    if (i0 >= ETOT) return;
    const int *sp, *dp, *rp; int* ce; int off;
    if (i0 < E0)            { sp = s0; dp = d0; rp = g_rp0; ce = g_ce0; off = 0; }
    else if (i0 < E0 + E1)  { sp = s1; dp = d1; rp = g_rp1; ce = g_ce1; off = E0; }
    else                    { sp = s2; dp = d2; rp = g_rp2; ce = g_ce2; off = E0 + E1; }
    int j = i0 - off;
    int4 ss = *(const int4*)&sp[j];
    int4 dd = *(const int4*)&dp[j];
    int4 sl = *(const int4*)&g_slot[i0];
    ce[rp[dd.x] + sl.x] = ss.x;
    ce[rp[dd.y] + sl.y] = ss.y;
    ce[rp[dd.z] + sl.z] = ss.z;
    ce[rp[dd.w] + sl.w] = ss.w;
}

// ---- K4: layer 0 — warp per node, lane = 2 batches (half2) ----
__global__ void k_agg0(const float* __restrict__ W0) {
    int warp = threadIdx.x >> 5, lane = threadIdx.x & 31;
    int node = blockIdx.x * 8 + warp;
    int beg = g_rp0[node], end = g_rp0[node + 1];
    float ax = 0.f, ay = 0.f;
    for (int c = beg; c < end; c += 32) {
        int nchunk = min(32, end - c);
        int idx = (c + lane < end) ? g_ce0[c + lane] : 0;
#pragma unroll 4
        for (int k = 0; k < nchunk; k++) {
            int src = __shfl_sync(0xffffffffu, idx, k);
            float2 f = __half22float2(*(const __half2*)&g_xT[src * Bb + 2 * lane]);
            ax += f.x; ay += f.y;
        }
    }
    float inv = 1.f / fmaxf((float)(end - beg), 1.f);
    float s0 = ax * inv, s1 = ay * inv;
    float mn = fminf(s0, s1), mx = fmaxf(s0, s1);
#pragma unroll
    for (int off = 16; off; off >>= 1) {
        mn = fminf(mn, __shfl_xor_sync(0xffffffffu, mn, off));
        mx = fmaxf(mx, __shfl_xor_sync(0xffffffffu, mx, off));
    }
    __half2 o0[4], o1[4];
#pragma unroll
    for (int h = 0; h < 4; h++) {
        float wa = W0[2 * h], wb = W0[2 * h + 1];
        float loa = (wa >= 0.f) ? wa * mn : wa * mx;
        float hia = (wa >= 0.f) ? wa * mx : wa * mn;
        float lob = (wb >= 0.f) ? wb * mn : wb * mx;
        float hib = (wb >= 0.f) ? wb * mx : wb * mn;
        float ia = 1.f / (hia - loa + EPSV), ib = 1.f / (hib - lob + EPSV);
        o0[h] = __floats2half2_rn(fmaxf((wa * s0 - loa) * ia, 0.f),
                                  fmaxf((wb * s0 - lob) * ib, 0.f));
        o1[h] = __floats2half2_rn(fmaxf((wa * s1 - loa) * ia, 0.f),
                                  fmaxf((wb * s1 - lob) * ib, 0.f));
    }
    *(uint4*)&g_d1[(node * Bb + 2 * lane) * 8]     = *(uint4*)o0;
    *(uint4*)&g_d1[(node * Bb + 2 * lane + 1) * 8] = *(uint4*)o1;
}

// ---- K5/K6: layers 1/2 — warp per node, lane = 2 batches x 8 h ----
__global__ void k_aggL(const float* __restrict__ W, int L) {
    const int*    rp  = (L == 1) ? g_rp1 : g_rp2;
    const int*    ce  = (L == 1) ? g_ce1 : g_ce2;
    const __half* din = (L == 1) ? g_d1  : g_d2;
    const int     m   = (L == 1) ? M1    : M2;
    __shared__ float sW[64];
    if (threadIdx.x < 64) sW[threadIdx.x] = W[threadIdx.x];
    __syncthreads();
    int warp = threadIdx.x >> 5, lane = threadIdx.x & 31;
    int node = blockIdx.x * 8 + warp;
    if (node >= m) return;
    int beg = rp[node], end = rp[node + 1];
    float a0[8], a1[8];
#pragma unroll
    for (int h = 0; h < 8; h++) { a0[h] = 0.f; a1[h] = 0.f; }
    for (int c = beg; c < end; c += 32) {
        int nchunk = min(32, end - c);
        int idx = (c + lane < end) ? ce[c + lane] : 0;
#pragma unroll 2
        for (int k = 0; k < nchunk; k++) {
            int src = __shfl_sync(0xffffffffu, idx, k);
            const uint4* p = (const uint4*)&din[(src * Bb + 2 * lane) * 8];
            uint4 r0 = p[0], r1 = p[1];
            float2 f;
            f = __half22float2(*(__half2*)&r0.x); a0[0] += f.x; a0[1] += f.y;
            f = __half22float2(*(__half2*)&r0.y); a0[2] += f.x; a0[3] += f.y;
            f = __half22float2(*(__half2*)&r0.z); a0[4] += f.x; a0[5] += f.y;
            f = __half22float2(*(__half2*)&r0.w); a0[6] += f.x; a0[7] += f.y;
            f = __half22float2(*(__half2*)&r1.x); a1[0] += f.x; a1[1] += f.y;
            f = __half22float2(*(__half2*)&r1.y); a1[2] += f.x; a1[3] += f.y;
            f = __half22float2(*(__half2*)&r1.z); a1[4] += f.x; a1[5] += f.y;
            f = __half22float2(*(__half2*)&r1.w); a1[6] += f.x; a1[7] += f.y;
        }
    }
    float inv = 1.f / fmaxf((float)(end - beg), 1.f);
    float t0[8], t1[8], mn[8], mx[8];
#pragma unroll
    for (int h = 0; h < 8; h++) {
        float v0 = 0.f, v1 = 0.f;
#pragma unroll
        for (int d = 0; d < 8; d++) {
            float w = sW[h * 8 + d];
            v0 += w * a0[d]; v1 += w * a1[d];
        }
        t0[h] = v0 * inv; t1[h] = v1 * inv;
        mn[h] = fminf(t0[h], t1[h]); mx[h] = fmaxf(t0[h], t1[h]);
    }
#pragma unroll
    for (int off = 16; off; off >>= 1) {
#pragma unroll
        for (int h = 0; h < 8; h++) {
            mn[h] = fminf(mn[h], __shfl_xor_sync(0xffffffffu, mn[h], off));
            mx[h] = fmaxf(mx[h], __shfl_xor_sync(0xffffffffu, mx[h], off));
        }
    }
    if (L == 1) {
        __half2 p0[4], p1[4];
#pragma unroll
        for (int h = 0; h < 4; h++) {
            float ia = 1.f / (mx[2 * h] - mn[2 * h] + EPSV);
            float ib = 1.f / (mx[2 * h + 1] - mn[2 * h + 1] + EPSV);
            p0[h] = __floats2half2_rn(fmaxf((t0[2 * h] - mn[2 * h]) * ia, 0.f),
                                      fmaxf((t0[2 * h + 1] - mn[2 * h + 1]) * ib, 0.f));
            p1[h] = __floats2half2_rn(fmaxf((t1[2 * h] - mn[2 * h]) * ia, 0.f),
                                      fmaxf((t1[2 * h + 1] - mn[2 * h + 1]) * ib, 0.f));
        }
        *(uint4*)&g_d2[(node * Bb + 2 * lane) * 8]     = *(uint4*)p0;
        *(uint4*)&g_d2[(node * Bb + 2 * lane + 1) * 8] = *(uint4*)p1;
    } else {
        float4 q0a, q0b, q1a, q1b;
        float o0[8], o1[8];
#pragma unroll
        for (int h = 0; h < 8; h++) {
            float iv = 1.f / (mx[h] - mn[h] + EPSV);
            o0[h] = fmaxf((t0[h] - mn[h]) * iv, 0.f);
            o1[h] = fmaxf((t1[h] - mn[h]) * iv, 0.f);
        }
        q0a = make_float4(o0[0], o0[1], o0[2], o0[3]);
        q0b = make_float4(o0[4], o0[5], o0[6], o0[7]);
        q1a = make_float4(o1[0], o1[1], o1[2], o1[3]);
        q1b = make_float4(o1[4], o1[5], o1[6], o1[7]);
        float4* q = (float4*)&g_d3[(node * Bb + 2 * lane) * 8];
        q[0] = q0a; q[1] = q0b; q[2] = q1a; q[3] = q1b;
    }
}

// ---- K7: final dot ----
__global__ void k_out(const float* __restrict__ Wout, const float* __restrict__ bout,
                      float* __restrict__ out) {
    int b = blockIdx.x;
    float p = 0.f;
    for (int idx = threadIdx.x; idx < M2 * 8; idx += blockDim.x) {
        p += g_d3[((idx >> 3) * Bb + b) * 8 + (idx & 7)] * Wout[idx];
    }
    __shared__ float sh[128];
    sh[threadIdx.x] = p;
    __syncthreads();
    for (int s = 64; s; s >>= 1) {
        if (threadIdx.x < (unsigned)s) sh[threadIdx.x] += sh[threadIdx.x + s];
        __syncthreads();
    }
    if (threadIdx.x == 0) out[b] = sh[0] + bout[0];
}

extern "C" void kernel_launch(void* const* d_in, const int* in_sizes, int n_in,
                              void* d_out, int out_size) {
    const float* x    = (const float*)d_in[0];
    const int*   e0s  = (const int*)d_in[1];
    const int*   e0d  = (const int*)d_in[2];
    const int*   e1s  = (const int*)d_in[3];
    const int*   e1d  = (const int*)d_in[4];
    const int*   e2s  = (const int*)d_in[5];
    const int*   e2d  = (const int*)d_in[6];
    const float* W0   = (const float*)d_in[7];
    const float* W1   = (const float*)d_in[8];
    const float* W2   = (const float*)d_in[9];
    const float* Wout = (const float*)d_in[10];
    const float* bout = (const float*)d_in[11];
    float* out = (float*)d_out;

    k_pre<<<TB + EB, 256>>>(x, e0d, e1d, e2d);
    k_scan<<<3, 1024>>>();
    k_fill<<<EB, 256>>>(e0s, e0d, e1s, e1d, e2s, e2d);
    k_agg0<<<M0 / 8, 256>>>(W0);
    k_aggL<<<(M1 + 7) / 8, 256>>>(W1, 1);
    k_aggL<<<(M2 + 7) / 8, 256>>>(W2, 2);
    k_out<<<Bb, 128>>>(Wout, bout, out);
}